// round 5
// baseline (speedup 1.0000x reference)
#include <cuda_runtime.h>
#include <cstdint>

typedef unsigned long long u64;

// ---- packed f32x2 helpers --------------------------------------------------
__device__ __forceinline__ u64 pk2(float a, float b) {
    u64 r; asm("mov.b64 %0, {%1,%2};" : "=l"(r) : "f"(a), "f"(b)); return r;
}
__device__ __forceinline__ void up2(u64 v, float& a, float& b) {
    asm("mov.b64 {%0,%1}, %2;" : "=f"(a), "=f"(b) : "l"(v));
}
__device__ __forceinline__ u64 fma2(u64 a, u64 b, u64 c) {
    u64 d; asm("fma.rn.f32x2 %0, %1, %2, %3;" : "=l"(d) : "l"(a), "l"(b), "l"(c)); return d;
}
__device__ __forceinline__ u64 add2(u64 a, u64 b) {
    u64 d; asm("add.rn.f32x2 %0, %1, %2;" : "=l"(d) : "l"(a), "l"(b)); return d;
}

// ---- problem constants -----------------------------------------------------
constexpr int D      = 64;
constexpr int M      = 2048;
constexpr int K      = 8;
constexpr int NTOK   = 32768;       // B*S
constexpr int PAIRS  = 16;          // token pairs per CTA (tok p, tok p+16)
constexpr int TPC    = 32;          // tokens per CTA
constexpr int CT     = 64;          // codes per staged tile
constexpr int NTILES = M / CT;      // 32
constexpr int NT     = 64;          // threads per CTA (2 warps)
constexpr int NCTA   = NTOK / TPC;  // 1024  (occ 7 -> conc 1036: single wave)

// ---- dynamic smem layout (bytes) -------------------------------------------
constexpr int OFF_RP  = 0;                        // u64   RP[D][PAIRS]    8192
constexpr int OFF_CP  = OFF_RP + D * PAIRS * 8;   // float CP[D][CT]      16384
constexpr int OFF_C2  = OFF_CP + D * CT * 4;      // float C2[CT]           256
constexpr int OFF_R2  = OFF_C2 + CT * 4;          // u64   R2s[PAIRS]       128
constexpr int OFF_CHO = OFF_R2 + PAIRS * 8;       // int2  CHO[PAIRS]       128
constexpr int SMEMB   = OFF_CHO + PAIRS * 8;      // 25088
constexpr int OFF_MN  = OFF_CP;                   // float4 MN[NT][4] aliases CP

// 64 threads; thread (a = t&3, cg = t>>2) owns pairs {2a,2a+1,2a+8,2a+9}
// x codes {4cg..4cg+3} -> 16 FMA2 accumulators (4x4 block, 32 regs).
// Numerics replicate the reference bit-for-bit (rel_err 0.0 in R1-R4):
// ascending-d FMA chains for cross/r2; d2 = (r2 - 2*cross) + c2 with c2 =
// two ascending 32-dim half-chains summed; strict-< ascending argmin +
// lexicographic (d2, idx) cross-thread merge over ascending code blocks.
__global__ void __launch_bounds__(NT, 7)
rvq_kernel(const float* __restrict__ x, const float* __restrict__ cb,
           float* __restrict__ qout, float* __restrict__ idxout)
{
    extern __shared__ __align__(16) char sm[];
    u64*    RP  = (u64*)(sm + OFF_RP);
    float*  CP  = (float*)(sm + OFF_CP);
    float*  C2  = (float*)(sm + OFF_C2);
    u64*    R2s = (u64*)(sm + OFF_R2);
    int2*   CHO = (int2*)(sm + OFF_CHO);
    float4* MN  = (float4*)(sm + OFF_MN);

    const int t    = threadIdx.x;
    const int base = blockIdx.x * TPC;
    const int pq   = t & 15;        // pair for init/update/output roles
    const int qh   = t >> 4;        // dim quarter (0..3)
    const int tok0 = base + pq;
    const int tok1 = tok0 + PAIRS;
    const int a    = t & 3;         // pair stripe
    const int cg   = t >> 2;        // code group (0..15)

    const u64 NEG1 = pk2(-1.0f, -1.0f);
    const u64 NEG2 = pk2(-2.0f, -2.0f);

    // ---- init: pack x into RP (pair p = tokens p, p+16) ----
    {
        const float4* xa = (const float4*)(x + (size_t)tok0 * D) + qh * 4;
        const float4* xb = (const float4*)(x + (size_t)tok1 * D) + qh * 4;
        #pragma unroll
        for (int i = 0; i < 4; i++) {
            float4 va = xa[i], vb = xb[i];
            int d = qh * 16 + i * 4;
            RP[(d+0)*PAIRS + pq] = pk2(va.x, vb.x);
            RP[(d+1)*PAIRS + pq] = pk2(va.y, vb.y);
            RP[(d+2)*PAIRS + pq] = pk2(va.z, vb.z);
            RP[(d+3)*PAIRS + pq] = pk2(va.w, vb.w);
        }
    }
    __syncthreads();

    for (int k = 0; k < K; k++) {
        const float* cbk = cb + (size_t)k * M * D;

        // ---- r2 per pair: ascending-d packed FMA chain ----
        // (ordered vs RP by the init/update barrier before, tile-0 staging
        //  barrier after; R2s region untouched by staging)
        if (t < PAIRS) {
            u64 n2 = 0ull;
            #pragma unroll 8
            for (int d = 0; d < D; d++) { u64 v = RP[d*PAIRS + t]; n2 = fma2(v, v, n2); }
            R2s[t] = n2;
        }

        float mlo[4], mhi[4]; int ilo[4], ihi[4];
        #pragma unroll
        for (int s = 0; s < 4; s++) {
            mlo[s] = 3.402823466e38f; mhi[s] = 3.402823466e38f; ilo[s] = 0; ihi[s] = 0;
        }

        for (int tile = 0; tile < NTILES; tile++) {
            // ---- stage 64 codes (one per thread); c2 = two half-chains ----
            {
                const int c0 = tile * CT + t;
                const float4* s0 = (const float4*)(cbk + (size_t)c0 * D);
                float c2a = 0.0f, c2b = 0.0f;
                #pragma unroll
                for (int i = 0; i < 8; i++) {          // dims 0..31
                    float4 v = s0[i]; int d = 4*i;
                    CP[(d+0)*CT + t] = v.x; CP[(d+1)*CT + t] = v.y;
                    CP[(d+2)*CT + t] = v.z; CP[(d+3)*CT + t] = v.w;
                    c2a = fmaf(v.x,v.x,c2a); c2a = fmaf(v.y,v.y,c2a);
                    c2a = fmaf(v.z,v.z,c2a); c2a = fmaf(v.w,v.w,c2a);
                }
                #pragma unroll
                for (int i = 8; i < 16; i++) {         // dims 32..63
                    float4 v = s0[i]; int d = 4*i;
                    CP[(d+0)*CT + t] = v.x; CP[(d+1)*CT + t] = v.y;
                    CP[(d+2)*CT + t] = v.z; CP[(d+3)*CT + t] = v.w;
                    c2b = fmaf(v.x,v.x,c2b); c2b = fmaf(v.y,v.y,c2b);
                    c2b = fmaf(v.z,v.z,c2b); c2b = fmaf(v.w,v.w,c2b);
                }
                C2[t] = c2a + c2b;
            }
            __syncthreads();

            // ---- cross: 4 pairs x 4 codes per thread, ascending-d chains ----
            u64 acc[4][4];
            #pragma unroll
            for (int p = 0; p < 4; p++)
                #pragma unroll
                for (int c = 0; c < 4; c++) acc[p][c] = 0ull;

            #pragma unroll 4
            for (int d = 0; d < D; d++) {
                const u64* rp = RP + d * PAIRS;
                ulonglong2 rA = *(const ulonglong2*)(rp + 2*a);      // pairs 2a,2a+1
                ulonglong2 rB = *(const ulonglong2*)(rp + 2*a + 8);  // pairs 2a+8,2a+9
                float4 cf = *(const float4*)(CP + d*CT + cg*4);
                u64 cc0 = pk2(cf.x, cf.x), cc1 = pk2(cf.y, cf.y);
                u64 cc2 = pk2(cf.z, cf.z), cc3 = pk2(cf.w, cf.w);
                u64 rr[4] = {rA.x, rA.y, rB.x, rB.y};
                #pragma unroll
                for (int p = 0; p < 4; p++) {
                    acc[p][0] = fma2(rr[p], cc0, acc[p][0]);
                    acc[p][1] = fma2(rr[p], cc1, acc[p][1]);
                    acc[p][2] = fma2(rr[p], cc2, acc[p][2]);
                    acc[p][3] = fma2(rr[p], cc3, acc[p][3]);
                }
            }

            // ---- d2 + running argmin (ascending code order per pair) ----
            u64 r2v[4];
            r2v[0] = R2s[2*a];   r2v[1] = R2s[2*a+1];
            r2v[2] = R2s[2*a+8]; r2v[3] = R2s[2*a+9];
            const int jb = tile * CT + cg * 4;
            #pragma unroll
            for (int c = 0; c < 4; c++) {
                float c2s = C2[cg*4 + c];
                u64 c2dup = pk2(c2s, c2s);
                #pragma unroll
                for (int p = 0; p < 4; p++) {
                    float lo, hi;
                    up2(add2(fma2(acc[p][c], NEG2, r2v[p]), c2dup), lo, hi);
                    if (lo < mlo[p]) { mlo[p] = lo; ilo[p] = jb + c; }
                    if (hi < mhi[p]) { mhi[p] = hi; ihi[p] = jb + c; }
                }
            }
            __syncthreads();   // CP/C2 consumed; safe to restage / alias MN
        }

        // ---- cross-thread argmin merge (MN aliases CP) ----
        #pragma unroll
        for (int s = 0; s < 4; s++)
            MN[t*4 + s] = make_float4(mlo[s], __int_as_float(ilo[s]),
                                      mhi[s], __int_as_float(ihi[s]));
        __syncthreads();

        if (t < PAIRS) {
            const int p  = t;
            const int pa = (p & 7) >> 1;             // stripe of pair p
            const int sl = (p >> 3) * 2 + (p & 1);   // slot within stripe
            float g0 = 3.402823466e38f, g1 = g0;
            int gi0 = 0, gi1 = 0;
            #pragma unroll
            for (int c = 0; c < 16; c++) {   // ascending cg = ascending code blocks
                float4 v = MN[(c*4 + pa)*4 + sl];
                float va = v.x, vb = v.z;
                int ia = __float_as_int(v.y), ib = __float_as_int(v.w);
                if (va < g0 || (va == g0 && ia < gi0)) { g0 = va; gi0 = ia; }
                if (vb < g1 || (vb == g1 && ib < gi1)) { g1 = vb; gi1 = ib; }
            }
            CHO[p] = make_int2(gi0, gi1);
            if (idxout) {
                idxout[(size_t)k * NTOK + base + p]         = (float)gi0;
                idxout[(size_t)k * NTOK + base + PAIRS + p] = (float)gi1;
            }
        }
        __syncthreads();

        // ---- residual update: RP[d][p] -= code (exact fma(-1,c,r)) ----
        {
            int2 ch = CHO[pq];
            const float4* ca = (const float4*)(cbk + (size_t)ch.x * D) + qh * 4;
            const float4* cw = (const float4*)(cbk + (size_t)ch.y * D) + qh * 4;
            #pragma unroll
            for (int i = 0; i < 4; i++) {
                float4 u = ca[i], w = cw[i];
                int d = qh * 16 + i * 4;
                RP[(d+0)*PAIRS+pq] = fma2(pk2(u.x, w.x), NEG1, RP[(d+0)*PAIRS+pq]);
                RP[(d+1)*PAIRS+pq] = fma2(pk2(u.y, w.y), NEG1, RP[(d+1)*PAIRS+pq]);
                RP[(d+2)*PAIRS+pq] = fma2(pk2(u.z, w.z), NEG1, RP[(d+2)*PAIRS+pq]);
                RP[(d+3)*PAIRS+pq] = fma2(pk2(u.w, w.w), NEG1, RP[(d+3)*PAIRS+pq]);
            }
        }
        __syncthreads();
    }

    // ---- output: quantized = x - residual (exact elementwise) ----
    {
        const float4* xa = (const float4*)(x + (size_t)tok0 * D) + qh * 4;
        const float4* xb = (const float4*)(x + (size_t)tok1 * D) + qh * 4;
        float4* qa = (float4*)(qout + (size_t)tok0 * D) + qh * 4;
        float4* qb = (float4*)(qout + (size_t)tok1 * D) + qh * 4;
        #pragma unroll
        for (int i = 0; i < 4; i++) {
            float4 va = xa[i], vb = xb[i];
            float4 oa, ob; float lo, hi;
            int d = qh * 16 + i * 4;
            up2(RP[(d+0)*PAIRS+pq], lo, hi); oa.x = va.x - lo; ob.x = vb.x - hi;
            up2(RP[(d+1)*PAIRS+pq], lo, hi); oa.y = va.y - lo; ob.y = vb.y - hi;
            up2(RP[(d+2)*PAIRS+pq], lo, hi); oa.z = va.z - lo; ob.z = vb.z - hi;
            up2(RP[(d+3)*PAIRS+pq], lo, hi); oa.w = va.w - lo; ob.w = vb.w - hi;
            qa[i] = oa; qb[i] = ob;
        }
    }
}

extern "C" void kernel_launch(void* const* d_in, const int* in_sizes, int n_in,
                              void* d_out, int out_size)
{
    const float* x  = (const float*)d_in[0];
    const float* cb = (const float*)d_in[1];
    if (n_in >= 2 && in_sizes[0] == K * M * D && in_sizes[1] == NTOK * D) {
        x  = (const float*)d_in[1];
        cb = (const float*)d_in[0];
    }
    float* q = (float*)d_out;
    float* idxf = (out_size >= NTOK * D + K * NTOK) ? (q + (size_t)NTOK * D) : nullptr;

    cudaFuncSetAttribute(rvq_kernel, cudaFuncAttributeMaxDynamicSharedMemorySize, SMEMB);
    rvq_kernel<<<NCTA, NT, SMEMB>>>(x, cb, q, idxf);
}

// round 6
// speedup vs baseline: 1.1719x; 1.1719x over previous
#include <cuda_runtime.h>
#include <cstdint>

typedef unsigned long long u64;

// ---- packed f32x2 helpers --------------------------------------------------
__device__ __forceinline__ u64 pk2(float a, float b) {
    u64 r; asm("mov.b64 %0, {%1,%2};" : "=l"(r) : "f"(a), "f"(b)); return r;
}
__device__ __forceinline__ void up2(u64 v, float& a, float& b) {
    asm("mov.b64 {%0,%1}, %2;" : "=f"(a), "=f"(b) : "l"(v));
}
__device__ __forceinline__ u64 fma2(u64 a, u64 b, u64 c) {
    u64 d; asm("fma.rn.f32x2 %0, %1, %2, %3;" : "=l"(d) : "l"(a), "l"(b), "l"(c)); return d;
}
__device__ __forceinline__ u64 add2(u64 a, u64 b) {
    u64 d; asm("add.rn.f32x2 %0, %1, %2;" : "=l"(d) : "l"(a), "l"(b)); return d;
}

// ---- problem constants -----------------------------------------------------
constexpr int D      = 64;
constexpr int M      = 2048;
constexpr int K      = 8;
constexpr int NTOK   = 32768;       // B*S
constexpr int PAIRS  = 16;          // token pairs per CTA (tok p, tok p+16)
constexpr int TPC    = 32;          // tokens per CTA
constexpr int CT     = 128;         // codes per staged tile
constexpr int NTILES = M / CT;      // 16
constexpr int NT     = 64;          // threads per CTA (2 warps)
constexpr int NCTA   = NTOK / TPC;  // 1024

// ---- dynamic smem layout (bytes) -------------------------------------------
constexpr int OFF_RP  = 0;                        // u64   RP[D][PAIRS]    8192
constexpr int OFF_CP  = OFF_RP + D * PAIRS * 8;   // float CP[D][CT]      32768
constexpr int OFF_C2  = OFF_CP + D * CT * 4;      // float C2[CT]           512
constexpr int OFF_R2  = OFF_C2 + CT * 4;          // u64   R2s[PAIRS]       128
constexpr int OFF_CHO = OFF_R2 + PAIRS * 8;       // int2  CHO[PAIRS]       128
constexpr int SMEMB   = OFF_CHO + PAIRS * 8;      // 41728
constexpr int OFF_MN  = OFF_CP;                   // float4 MN[NT][4] aliases CP

// 64 threads; thread (a = t&3, cg = t>>2) owns pairs {2a,2a+1,2a+8,2a+9}
// x codes {8cg..8cg+7} -> 32 FMA2 accumulators (4x8 block, ~64 regs).
// Numerics replicate the reference bit-for-bit (rel_err 0.0 in R1-R5):
// ascending-d FMA chains for cross/r2; d2 = (r2 - 2*cross) + c2 with c2 =
// two ascending 32-dim half-chains summed; strict-< ascending argmin +
// lexicographic (d2, idx) cross-thread merge over ascending code blocks.
__global__ void __launch_bounds__(NT, 5)
rvq_kernel(const float* __restrict__ x, const float* __restrict__ cb,
           float* __restrict__ qout, float* __restrict__ idxout)
{
    extern __shared__ __align__(16) char sm[];
    u64*    RP  = (u64*)(sm + OFF_RP);
    float*  CP  = (float*)(sm + OFF_CP);
    float*  C2  = (float*)(sm + OFF_C2);
    u64*    R2s = (u64*)(sm + OFF_R2);
    int2*   CHO = (int2*)(sm + OFF_CHO);
    float4* MN  = (float4*)(sm + OFF_MN);

    const int t    = threadIdx.x;
    const int base = blockIdx.x * TPC;
    const int pq   = t & 15;        // pair for init/update/output roles
    const int qh   = t >> 4;        // dim quarter (0..3)
    const int tok0 = base + pq;
    const int tok1 = tok0 + PAIRS;
    const int a    = t & 3;         // pair stripe
    const int cg   = t >> 2;        // code group (0..15), 8 codes each

    const u64 NEG1 = pk2(-1.0f, -1.0f);
    const u64 NEG2 = pk2(-2.0f, -2.0f);

    // ---- init: pack x into RP (pair p = tokens p, p+16) ----
    {
        const float4* xa = (const float4*)(x + (size_t)tok0 * D) + qh * 4;
        const float4* xb = (const float4*)(x + (size_t)tok1 * D) + qh * 4;
        #pragma unroll
        for (int i = 0; i < 4; i++) {
            float4 va = xa[i], vb = xb[i];
            int d = qh * 16 + i * 4;
            RP[(d+0)*PAIRS + pq] = pk2(va.x, vb.x);
            RP[(d+1)*PAIRS + pq] = pk2(va.y, vb.y);
            RP[(d+2)*PAIRS + pq] = pk2(va.z, vb.z);
            RP[(d+3)*PAIRS + pq] = pk2(va.w, vb.w);
        }
    }
    __syncthreads();

    for (int k = 0; k < K; k++) {
        const float* cbk = cb + (size_t)k * M * D;

        // ---- r2 per pair: ascending-d packed FMA chain ----
        if (t < PAIRS) {
            u64 n2 = 0ull;
            #pragma unroll 8
            for (int d = 0; d < D; d++) { u64 v = RP[d*PAIRS + t]; n2 = fma2(v, v, n2); }
            R2s[t] = n2;
        }

        float mlo[4], mhi[4]; int ilo[4], ihi[4];
        #pragma unroll
        for (int s = 0; s < 4; s++) {
            mlo[s] = 3.402823466e38f; mhi[s] = 3.402823466e38f; ilo[s] = 0; ihi[s] = 0;
        }

        for (int tile = 0; tile < NTILES; tile++) {
            // ---- stage 128 codes (codes t and t+64); c2 = two half-chains ----
            {
                const int c0 = tile * CT + t;
                const float4* s0 = (const float4*)(cbk + (size_t)c0 * D);
                const float4* s1 = (const float4*)(cbk + (size_t)(c0 + 64) * D);
                float c2a = 0.0f, c2b = 0.0f, c2c = 0.0f, c2d = 0.0f;
                #pragma unroll
                for (int i = 0; i < 8; i++) {          // code t, dims 0..31
                    float4 v = s0[i]; int d = 4*i;
                    CP[(d+0)*CT + t] = v.x; CP[(d+1)*CT + t] = v.y;
                    CP[(d+2)*CT + t] = v.z; CP[(d+3)*CT + t] = v.w;
                    c2a = fmaf(v.x,v.x,c2a); c2a = fmaf(v.y,v.y,c2a);
                    c2a = fmaf(v.z,v.z,c2a); c2a = fmaf(v.w,v.w,c2a);
                }
                #pragma unroll
                for (int i = 8; i < 16; i++) {         // code t, dims 32..63
                    float4 v = s0[i]; int d = 4*i;
                    CP[(d+0)*CT + t] = v.x; CP[(d+1)*CT + t] = v.y;
                    CP[(d+2)*CT + t] = v.z; CP[(d+3)*CT + t] = v.w;
                    c2b = fmaf(v.x,v.x,c2b); c2b = fmaf(v.y,v.y,c2b);
                    c2b = fmaf(v.z,v.z,c2b); c2b = fmaf(v.w,v.w,c2b);
                }
                #pragma unroll
                for (int i = 0; i < 8; i++) {          // code t+64, dims 0..31
                    float4 v = s1[i]; int d = 4*i;
                    CP[(d+0)*CT + t+64] = v.x; CP[(d+1)*CT + t+64] = v.y;
                    CP[(d+2)*CT + t+64] = v.z; CP[(d+3)*CT + t+64] = v.w;
                    c2c = fmaf(v.x,v.x,c2c); c2c = fmaf(v.y,v.y,c2c);
                    c2c = fmaf(v.z,v.z,c2c); c2c = fmaf(v.w,v.w,c2c);
                }
                #pragma unroll
                for (int i = 8; i < 16; i++) {         // code t+64, dims 32..63
                    float4 v = s1[i]; int d = 4*i;
                    CP[(d+0)*CT + t+64] = v.x; CP[(d+1)*CT + t+64] = v.y;
                    CP[(d+2)*CT + t+64] = v.z; CP[(d+3)*CT + t+64] = v.w;
                    c2d = fmaf(v.x,v.x,c2d); c2d = fmaf(v.y,v.y,c2d);
                    c2d = fmaf(v.z,v.z,c2d); c2d = fmaf(v.w,v.w,c2d);
                }
                C2[t]    = c2a + c2b;
                C2[t+64] = c2c + c2d;
            }
            __syncthreads();

            // ---- cross: 4 pairs x 8 codes per thread, ascending-d chains ----
            u64 acc[4][8];
            #pragma unroll
            for (int p = 0; p < 4; p++)
                #pragma unroll
                for (int c = 0; c < 8; c++) acc[p][c] = 0ull;

            #pragma unroll 4
            for (int d = 0; d < D; d++) {
                const u64* rp = RP + d * PAIRS;
                ulonglong2 rA = *(const ulonglong2*)(rp + 2*a);      // pairs 2a,2a+1
                ulonglong2 rB = *(const ulonglong2*)(rp + 2*a + 8);  // pairs 2a+8,2a+9
                const float4* cf = (const float4*)(CP + d*CT + cg*8);
                float4 cA = cf[0], cB = cf[1];
                u64 cc0 = pk2(cA.x, cA.x), cc1 = pk2(cA.y, cA.y);
                u64 cc2 = pk2(cA.z, cA.z), cc3 = pk2(cA.w, cA.w);
                u64 cc4 = pk2(cB.x, cB.x), cc5 = pk2(cB.y, cB.y);
                u64 cc6 = pk2(cB.z, cB.z), cc7 = pk2(cB.w, cB.w);
                u64 rr[4] = {rA.x, rA.y, rB.x, rB.y};
                #pragma unroll
                for (int p = 0; p < 4; p++) {
                    acc[p][0] = fma2(rr[p], cc0, acc[p][0]);
                    acc[p][1] = fma2(rr[p], cc1, acc[p][1]);
                    acc[p][2] = fma2(rr[p], cc2, acc[p][2]);
                    acc[p][3] = fma2(rr[p], cc3, acc[p][3]);
                    acc[p][4] = fma2(rr[p], cc4, acc[p][4]);
                    acc[p][5] = fma2(rr[p], cc5, acc[p][5]);
                    acc[p][6] = fma2(rr[p], cc6, acc[p][6]);
                    acc[p][7] = fma2(rr[p], cc7, acc[p][7]);
                }
            }

            // ---- d2 + running argmin (ascending code order per pair) ----
            u64 r2v[4];
            r2v[0] = R2s[2*a];   r2v[1] = R2s[2*a+1];
            r2v[2] = R2s[2*a+8]; r2v[3] = R2s[2*a+9];
            const int jb = tile * CT + cg * 8;
            #pragma unroll
            for (int c = 0; c < 8; c++) {
                float c2s = C2[cg*8 + c];
                u64 c2dup = pk2(c2s, c2s);
                #pragma unroll
                for (int p = 0; p < 4; p++) {
                    float lo, hi;
                    up2(add2(fma2(acc[p][c], NEG2, r2v[p]), c2dup), lo, hi);
                    if (lo < mlo[p]) { mlo[p] = lo; ilo[p] = jb + c; }
                    if (hi < mhi[p]) { mhi[p] = hi; ihi[p] = jb + c; }
                }
            }
            __syncthreads();   // CP/C2 consumed; safe to restage / alias MN
        }

        // ---- cross-thread argmin merge (MN aliases CP) ----
        #pragma unroll
        for (int s = 0; s < 4; s++)
            MN[t*4 + s] = make_float4(mlo[s], __int_as_float(ilo[s]),
                                      mhi[s], __int_as_float(ihi[s]));
        __syncthreads();

        if (t < PAIRS) {
            const int p  = t;
            const int pa = (p & 7) >> 1;             // stripe of pair p
            const int sl = (p >> 3) * 2 + (p & 1);   // slot within stripe
            float g0 = 3.402823466e38f, g1 = g0;
            int gi0 = 0, gi1 = 0;
            #pragma unroll
            for (int c = 0; c < 16; c++) {   // ascending cg = ascending code blocks
                float4 v = MN[(c*4 + pa)*4 + sl];
                float va = v.x, vb = v.z;
                int ia = __float_as_int(v.y), ib = __float_as_int(v.w);
                if (va < g0 || (va == g0 && ia < gi0)) { g0 = va; gi0 = ia; }
                if (vb < g1 || (vb == g1 && ib < gi1)) { g1 = vb; gi1 = ib; }
            }
            CHO[p] = make_int2(gi0, gi1);
            if (idxout) {
                idxout[(size_t)k * NTOK + base + p]         = (float)gi0;
                idxout[(size_t)k * NTOK + base + PAIRS + p] = (float)gi1;
            }
        }
        __syncthreads();

        // ---- residual update: RP[d][p] -= code (exact fma(-1,c,r)) ----
        {
            int2 ch = CHO[pq];
            const float4* ca = (const float4*)(cbk + (size_t)ch.x * D) + qh * 4;
            const float4* cw = (const float4*)(cbk + (size_t)ch.y * D) + qh * 4;
            #pragma unroll
            for (int i = 0; i < 4; i++) {
                float4 u = ca[i], w = cw[i];
                int d = qh * 16 + i * 4;
                RP[(d+0)*PAIRS+pq] = fma2(pk2(u.x, w.x), NEG1, RP[(d+0)*PAIRS+pq]);
                RP[(d+1)*PAIRS+pq] = fma2(pk2(u.y, w.y), NEG1, RP[(d+1)*PAIRS+pq]);
                RP[(d+2)*PAIRS+pq] = fma2(pk2(u.z, w.z), NEG1, RP[(d+2)*PAIRS+pq]);
                RP[(d+3)*PAIRS+pq] = fma2(pk2(u.w, w.w), NEG1, RP[(d+3)*PAIRS+pq]);
            }
        }
        __syncthreads();
    }

    // ---- output: quantized = x - residual (exact elementwise) ----
    {
        const float4* xa = (const float4*)(x + (size_t)tok0 * D) + qh * 4;
        const float4* xb = (const float4*)(x + (size_t)tok1 * D) + qh * 4;
        float4* qa = (float4*)(qout + (size_t)tok0 * D) + qh * 4;
        float4* qb = (float4*)(qout + (size_t)tok1 * D) + qh * 4;
        #pragma unroll
        for (int i = 0; i < 4; i++) {
            float4 va = xa[i], vb = xb[i];
            float4 oa, ob; float lo, hi;
            int d = qh * 16 + i * 4;
            up2(RP[(d+0)*PAIRS+pq], lo, hi); oa.x = va.x - lo; ob.x = vb.x - hi;
            up2(RP[(d+1)*PAIRS+pq], lo, hi); oa.y = va.y - lo; ob.y = vb.y - hi;
            up2(RP[(d+2)*PAIRS+pq], lo, hi); oa.z = va.z - lo; ob.z = vb.z - hi;
            up2(RP[(d+3)*PAIRS+pq], lo, hi); oa.w = va.w - lo; ob.w = vb.w - hi;
            qa[i] = oa; qb[i] = ob;
        }
    }
}

extern "C" void kernel_launch(void* const* d_in, const int* in_sizes, int n_in,
                              void* d_out, int out_size)
{
    const float* x  = (const float*)d_in[0];
    const float* cb = (const float*)d_in[1];
    if (n_in >= 2 && in_sizes[0] == K * M * D && in_sizes[1] == NTOK * D) {
        x  = (const float*)d_in[1];
        cb = (const float*)d_in[0];
    }
    float* q = (float*)d_out;
    float* idxf = (out_size >= NTOK * D + K * NTOK) ? (q + (size_t)NTOK * D) : nullptr;

    cudaFuncSetAttribute(rvq_kernel, cudaFuncAttributeMaxDynamicSharedMemorySize, SMEMB);
    rvq_kernel<<<NCTA, NT, SMEMB>>>(x, cb, q, idxf);
}